// round 17
// baseline (speedup 1.0000x reference)
#include <cuda_runtime.h>
#include <cuda_fp16.h>
#include <cstdint>
#include <math.h>

#define T_NODES 16384
#define DIM     1024
#define NHEAD   16
#define HD      64
#define NGRAPH  32
#define NPG     512

// ---------------- scratch (device globals) ----------------
__device__ __half g_h_h  [(size_t)T_NODES * DIM];
__device__ __half g_qkv_h[(size_t)T_NODES * 3 * DIM];
__device__ __half g_attn_h[(size_t)T_NODES * DIM];
__device__ __half g_x1_h [(size_t)T_NODES * DIM];
__device__ __half g_tmp_h[(size_t)T_NODES * DIM];
__device__ __half g_f1_h [(size_t)T_NODES * 2 * DIM];
__device__ __half g_win_h [3 * DIM * DIM];
__device__ __half g_wout_h[DIM * DIM];
__device__ __half g_fw1_h [2 * DIM * DIM];
__device__ __half g_fw2_h [2 * DIM * DIM];

// ---------------- helpers ----------------
__device__ __forceinline__ uint32_t smem_u32(const void* p) {
    uint32_t a;
    asm("{ .reg .u64 t; cvta.to.shared.u64 t, %1; cvt.u32.u64 %0, t; }" : "=r"(a) : "l"(p));
    return a;
}
__device__ __forceinline__ void mma_f16(float* c, const uint32_t* a, const uint32_t* b) {
    asm volatile(
        "mma.sync.aligned.m16n8k16.row.col.f32.f16.f16.f32 "
        "{%0,%1,%2,%3}, {%4,%5,%6,%7}, {%8,%9}, {%0,%1,%2,%3};"
        : "+f"(c[0]), "+f"(c[1]), "+f"(c[2]), "+f"(c[3])
        : "r"(a[0]), "r"(a[1]), "r"(a[2]), "r"(a[3]), "r"(b[0]), "r"(b[1]));
}
__device__ __forceinline__ void ldsm4(uint32_t& r0, uint32_t& r1, uint32_t& r2,
                                      uint32_t& r3, uint32_t addr) {
    asm volatile("ldmatrix.sync.aligned.m8n8.x4.shared.b16 {%0,%1,%2,%3}, [%4];"
                 : "=r"(r0), "=r"(r1), "=r"(r2), "=r"(r3) : "r"(addr));
}
__device__ __forceinline__ void ldsm4t(uint32_t& r0, uint32_t& r1, uint32_t& r2,
                                       uint32_t& r3, uint32_t addr) {
    asm volatile("ldmatrix.sync.aligned.m8n8.x4.trans.shared.b16 {%0,%1,%2,%3}, [%4];"
                 : "=r"(r0), "=r"(r1), "=r"(r2), "=r"(r3) : "r"(addr));
}
__device__ __forceinline__ void cp16(uint32_t dst, const void* src) {
    asm volatile("cp.async.cg.shared.global [%0], [%1], 16;" :: "r"(dst), "l"(src));
}
__device__ __forceinline__ void cp_commit() { asm volatile("cp.async.commit_group;"); }
template <int N>
__device__ __forceinline__ void cp_wait() {
    asm volatile("cp.async.wait_group %0;" :: "n"(N));
}
__device__ __forceinline__ void mbar_init(uint32_t addr, uint32_t cnt) {
    asm volatile("mbarrier.init.shared.b64 [%0], %1;" :: "r"(addr), "r"(cnt) : "memory");
}
__device__ __forceinline__ void mbar_wait(uint32_t mbar, uint32_t parity) {
    asm volatile(
        "{\n\t.reg .pred P;\n\t"
        "WL%=:\n\t"
        "mbarrier.try_wait.parity.shared.b64 P, [%0], %1;\n\t"
        "@P bra WD%=;\n\t"
        "bra WL%=;\n\t"
        "WD%=:\n\t}"
        :: "r"(mbar), "r"(parity) : "memory");
}
__device__ __forceinline__ void mbar_arrive(uint32_t addr) {
    asm volatile("mbarrier.arrive.shared.b64 _, [%0];" :: "r"(addr) : "memory");
}
__device__ __forceinline__ void cp_arrive(uint32_t addr) {
    asm volatile("cp.async.mbarrier.arrive.noinc.shared.b64 [%0];"
                 :: "r"(addr) : "memory");
}

// ---------------- fused fp32 -> fp16 converts (one launch) ----------------
#define CN0 (T_NODES * DIM / 4)
#define CN1 (3 * DIM * DIM / 4)
#define CN2 (DIM * DIM / 4)
#define CN3 (2 * DIM * DIM / 4)
#define CN4 (2 * DIM * DIM / 4)
#define CNT (CN0 + CN1 + CN2 + CN3 + CN4)

__global__ void __launch_bounds__(256) f32_to_f16_all(
    const float* __restrict__ a0, __half* __restrict__ b0,
    const float* __restrict__ a1, __half* __restrict__ b1,
    const float* __restrict__ a2, __half* __restrict__ b2,
    const float* __restrict__ a3, __half* __restrict__ b3,
    const float* __restrict__ a4, __half* __restrict__ b4)
{
    int i = blockIdx.x * 256 + threadIdx.x;
    if (i >= CNT) return;
    const float* s; __half* d; int off;
    if (i < CN0)                       { s = a0; d = b0; off = i; }
    else if (i < CN0 + CN1)            { s = a1; d = b1; off = i - CN0; }
    else if (i < CN0 + CN1 + CN2)      { s = a2; d = b2; off = i - CN0 - CN1; }
    else if (i < CN0 + CN1 + CN2 + CN3){ s = a3; d = b3; off = i - CN0 - CN1 - CN2; }
    else                               { s = a4; d = b4; off = i - CN0 - CN1 - CN2 - CN3; }
    float4 v = ((const float4*)s)[off];
    __half2 x = __floats2half2_rn(v.x, v.y);
    __half2 y = __floats2half2_rn(v.z, v.w);
    uint2 u; u.x = *(uint32_t*)&x; u.y = *(uint32_t*)&y;
    ((uint2*)d)[off] = u;
}

// ============================ fp16 mma GEMM, mbarrier-decoupled pipeline =========
#define BM 128
#define BN 128
#define BKH 64
#define A_BYTES (BM * 128)
#define B_BYTES (BN * 128)
#define SLOT_BYTES (A_BYTES + B_BYTES)          // 32768
#define NSLOT 3
#define GEMM_SMEM (NSLOT * SLOT_BYTES + 576)    // slots + bias + mbarriers

template <bool RELU, bool ADDRES>
__global__ void __launch_bounds__(256, 2) gemm_h(
    const __half* __restrict__ A, const __half* __restrict__ B,
    const float* __restrict__ bias, __half* __restrict__ Ch,
    const __half* __restrict__ RresH, int M, int N, int K)
{
    extern __shared__ char smem[];
    const uint32_t sbase = smem_u32(smem);
    float* sbias = (float*)(smem + NSLOT * SLOT_BYTES);
    const uint32_t MB = sbase + NSLOT * SLOT_BYTES + 512;
    // full[s] = MB + s*8 ; empty[s] = MB + 24 + s*8

    const int tid = threadIdx.x;
    const int wid = tid >> 5, lane = tid & 31;
    const int g = lane >> 2, t = lane & 3;
    const int wm = wid & 1, wn = wid >> 1;
    const int m0 = blockIdx.y * BM, n0 = blockIdx.x * BN;

    if (tid < BN) sbias[tid] = bias[n0 + tid];
    if (tid == 0) {
#pragma unroll
        for (int s = 0; s < NSLOT; s++) {
            mbar_init(MB + s * 8, 256);
            mbar_init(MB + 24 + s * 8, 256);
        }
    }
    __syncthreads();

    const int lrow = lane & 15;
    const int lsel = lane >> 4;
    const int lxor = lane & 7;
    uint32_t aoff[4], boff[2];
#pragma unroll
    for (int mt = 0; mt < 4; mt++)
        aoff[mt] = (wm * 64 + mt * 16 + lrow) * 128;
#pragma unroll
    for (int pr = 0; pr < 2; pr++)
        boff[pr] = A_BYTES + (wn * 32 + pr * 16 + lrow) * 128;

    float acc[4][4][4];
#pragma unroll
    for (int i = 0; i < 4; i++)
#pragma unroll
        for (int j = 0; j < 4; j++)
#pragma unroll
            for (int q = 0; q < 4; q++) acc[i][j][q] = 0.f;

    const int NC = K / BKH;

    auto loadc = [&](int c, int slot) {
        const uint32_t sA = sbase + slot * SLOT_BYTES;
        const uint32_t sB = sA + A_BYTES;
        const __half* Ab = A + (size_t)m0 * K + c * BKH;
        const __half* Bb = B + (size_t)n0 * K + c * BKH;
#pragma unroll
        for (int i = 0; i < 4; i++) {
            int idx = tid + i * 256;
            int r = idx >> 3, ch = idx & 7;
            cp16(sA + r * 128 + ((ch ^ (r & 7)) << 4), Ab + (size_t)r * K + ch * 8);
        }
#pragma unroll
        for (int i = 0; i < 4; i++) {
            int idx = tid + i * 256;
            int r = idx >> 3, ch = idx & 7;
            cp16(sB + r * 128 + ((ch ^ (r & 7)) << 4), Bb + (size_t)r * K + ch * 8);
        }
    };

    // prologue: fill slots 0,1 and arm their full barriers
    loadc(0, 0); cp_arrive(MB + 0 * 8);
    loadc(1, 1); cp_arrive(MB + 1 * 8);

    uint32_t fph = 0, eph = 0;   // per-slot phase parity bits
    int slot = 0;
    for (int c = 0; c < NC; c++) {
        // consumer: wait tile ready
        mbar_wait(MB + slot * 8, (fph >> slot) & 1);
        fph ^= 1u << slot;

        // producer: prefetch chunk c+2 into slot ps
        if (c + 2 < NC) {
            int ps = slot + 2; if (ps >= NSLOT) ps -= NSLOT;
            if (c + 2 >= NSLOT) {            // slot reused: wait consumers of c-1
                mbar_wait(MB + 24 + ps * 8, (eph >> ps) & 1);
                eph ^= 1u << ps;
            }
            loadc(c + 2, ps);
            cp_arrive(MB + ps * 8);
        }

        const uint32_t slotb = sbase + slot * SLOT_BYTES;
#pragma unroll
        for (int ks = 0; ks < 4; ks++) {
            const uint32_t cb = (uint32_t)(((2 * ks + lsel) ^ lxor) << 4);
            uint32_t af[4][4];
#pragma unroll
            for (int mt = 0; mt < 4; mt++)
                ldsm4(af[mt][0], af[mt][1], af[mt][2], af[mt][3],
                      slotb + aoff[mt] + cb);
            uint32_t bf[4][2];
#pragma unroll
            for (int pr = 0; pr < 2; pr++) {
                uint32_t r0, r1, r2, r3;
                ldsm4(r0, r1, r2, r3, slotb + boff[pr] + cb);
                bf[2 * pr][0] = r0; bf[2 * pr][1] = r2;
                bf[2 * pr + 1][0] = r1; bf[2 * pr + 1][1] = r3;
            }
#pragma unroll
            for (int mt = 0; mt < 4; mt++)
#pragma unroll
                for (int nt = 0; nt < 4; nt++)
                    mma_f16(acc[mt][nt], af[mt], bf[nt]);
        }
        // consumer done with this slot
        mbar_arrive(MB + 24 + slot * 8);
        if (++slot >= NSLOT) slot = 0;
    }

    // epilogue (fp16 out, optional fp16 residual)
#pragma unroll
    for (int mt = 0; mt < 4; mt++) {
        const int row = m0 + wm * 64 + mt * 16 + g;
#pragma unroll
        for (int nt = 0; nt < 4; nt++) {
            const int cc = wn * 32 + nt * 8 + 2 * t;
            float b0 = sbias[cc], b1 = sbias[cc + 1];
            float r00 = acc[mt][nt][0] + b0, r01 = acc[mt][nt][1] + b1;
            float r10 = acc[mt][nt][2] + b0, r11 = acc[mt][nt][3] + b1;
            if (ADDRES) {
                float2 q0 = __half22float2(
                    *(const __half2*)(RresH + (size_t)row * N + n0 + cc));
                float2 q1 = __half22float2(
                    *(const __half2*)(RresH + (size_t)(row + 8) * N + n0 + cc));
                r00 += q0.x; r01 += q0.y; r10 += q1.x; r11 += q1.y;
            }
            if (RELU) {
                r00 = fmaxf(r00, 0.f); r01 = fmaxf(r01, 0.f);
                r10 = fmaxf(r10, 0.f); r11 = fmaxf(r11, 0.f);
            }
            __half2 h0 = __floats2half2_rn(r00, r01);
            __half2 h1 = __floats2half2_rn(r10, r11);
            *(__half2*)(Ch + (size_t)row * N + n0 + cc) = h0;
            *(__half2*)(Ch + (size_t)(row + 8) * N + n0 + cc) = h1;
        }
    }
}

// ============================ FlashAttention kernel (R16 winner, unchanged) ======
#define AST_K 8192
#define AST   16384
#define ASOFF 16384
#define ATTN_SMEM (16384 + 3 * AST)   // 65536 -> 2 CTAs/SM

__global__ void __launch_bounds__(256, 2) attn_flash(
    const __half* __restrict__ qkvh, __half* __restrict__ oh)
{
    extern __shared__ char smc[];
    const uint32_t sb = smem_u32(smc);

    const int tid = threadIdx.x;
    const int w = tid >> 5, lane = tid & 31;
    const int g = lane >> 2, t = lane & 3;
    const int qt = blockIdx.x, hh = blockIdx.y, gg = blockIdx.z;
    const size_t nb = (size_t)gg * NPG;
    const int qrow0 = qt * 128;

    const int lr = tid >> 3, lch = tid & 7;

#pragma unroll
    for (int i = 0; i < 4; i++) {
        int r = lr + i * 32;
        cp16(sb + r * 128 + (((uint32_t)lch ^ (r & 7)) << 4),
             qkvh + (nb + qrow0 + r) * 3072 + hh * 64 + lch * 8);
    }
    cp_commit();
#pragma unroll
    for (int j = 0; j < 2; j++) {
#pragma unroll
        for (int i = 0; i < 2; i++) {
            int r = lr + i * 32;
            cp16(sb + ASOFF + j * AST + r * 128 + (((uint32_t)lch ^ (r & 7)) << 4),
                 qkvh + (nb + j * 64 + r) * 3072 + 1024 + hh * 64 + lch * 8);
        }
#pragma unroll
        for (int i = 0; i < 2; i++) {
            int r = lr + i * 32;
            cp16(sb + ASOFF + j * AST + AST_K + r * 128 + (((uint32_t)lch ^ (r & 7)) << 4),
                 qkvh + (nb + j * 64 + r) * 3072 + 2048 + hh * 64 + lch * 8);
        }
        cp_commit();
    }

    cp_wait<2>();
    __syncthreads();

    const int lrow = lane & 15;
    const int lsel = lane >> 4;
    const int lxor = lane & 7;
    const uint32_t qaddr = sb + (w * 16 + lrow) * 128;
    uint32_t afq[4][4];
#pragma unroll
    for (int ks = 0; ks < 4; ks++)
        ldsm4(afq[ks][0], afq[ks][1], afq[ks][2], afq[ks][3],
              qaddr + (uint32_t)(((2 * ks + lsel) ^ lxor) << 4));

    uint32_t koff[4];
#pragma unroll
    for (int pr = 0; pr < 4; pr++)
        koff[pr] = (pr * 16 + lrow) * 128;

    const int lm = lane >> 3, lrr = lane & 7;
    const uint32_t vnodeb = (uint32_t)((lm & 1) * 8 + lrr);

    float Oa[8][4];
#pragma unroll
    for (int i = 0; i < 8; i++)
#pragma unroll
        for (int q = 0; q < 4; q++) Oa[i][q] = 0.f;
    float m0 = -1e30f, m1 = -1e30f, l0 = 0.f, l1 = 0.f;

    for (int kt = 0; kt < 8; kt++) {
        if (kt + 2 < 8) cp_wait<1>(); else cp_wait<0>();
        __syncthreads();
        if (kt + 2 < 8) {
            int j = (kt + 2) % 3;
#pragma unroll
            for (int i = 0; i < 2; i++) {
                int r = lr + i * 32;
                cp16(sb + ASOFF + j * AST + r * 128 + (((uint32_t)lch ^ (r & 7)) << 4),
                     qkvh + (nb + (kt + 2) * 64 + r) * 3072 + 1024 + hh * 64 + lch * 8);
            }
#pragma unroll
            for (int i = 0; i < 2; i++) {
                int r = lr + i * 32;
                cp16(sb + ASOFF + j * AST + AST_K + r * 128 + (((uint32_t)lch ^ (r & 7)) << 4),
                     qkvh + (nb + (kt + 2) * 64 + r) * 3072 + 2048 + hh * 64 + lch * 8);
            }
            cp_commit();
        }
        const uint32_t kb = sb + ASOFF + (kt % 3) * AST;

        float sc[8][4];
#pragma unroll
        for (int i = 0; i < 8; i++)
#pragma unroll
            for (int q = 0; q < 4; q++) sc[i][q] = 0.f;
#pragma unroll
        for (int ks = 0; ks < 4; ks++) {
            const uint32_t cb = (uint32_t)(((2 * ks + lsel) ^ lxor) << 4);
            uint32_t bf[8][2];
#pragma unroll
            for (int pr = 0; pr < 4; pr++) {
                uint32_t r0, r1, r2, r3;
                ldsm4(r0, r1, r2, r3, kb + koff[pr] + cb);
                bf[2 * pr][0] = r0; bf[2 * pr][1] = r2;
                bf[2 * pr + 1][0] = r1; bf[2 * pr + 1][1] = r3;
            }
#pragma unroll
            for (int nt = 0; nt < 8; nt++)
                mma_f16(sc[nt], afq[ks], bf[nt]);
        }

        float rm0 = -1e30f, rm1 = -1e30f;
#pragma unroll
        for (int nt = 0; nt < 8; nt++) {
            rm0 = fmaxf(rm0, fmaxf(sc[nt][0], sc[nt][1]));
            rm1 = fmaxf(rm1, fmaxf(sc[nt][2], sc[nt][3]));
        }
        rm0 = fmaxf(rm0, __shfl_xor_sync(0xffffffffu, rm0, 1));
        rm0 = fmaxf(rm0, __shfl_xor_sync(0xffffffffu, rm0, 2));
        rm1 = fmaxf(rm1, __shfl_xor_sync(0xffffffffu, rm1, 1));
        rm1 = fmaxf(rm1, __shfl_xor_sync(0xffffffffu, rm1, 2));
        const float m0n = fmaxf(m0, rm0 * 0.125f);
        const float m1n = fmaxf(m1, rm1 * 0.125f);
        const float c0 = __expf(m0 - m0n), c1 = __expf(m1 - m1n);
#pragma unroll
        for (int i = 0; i < 8; i++) {
            Oa[i][0] *= c0; Oa[i][1] *= c0;
            Oa[i][2] *= c1; Oa[i][3] *= c1;
        }
        l0 *= c0; l1 *= c1;
        m0 = m0n; m1 = m1n;

        uint32_t ap[4][4];
        float s0 = 0.f, s1 = 0.f;
#pragma unroll
        for (int j = 0; j < 4; j++) {
            float p00 = __expf(sc[2 * j][0] * 0.125f - m0n);
            float p01 = __expf(sc[2 * j][1] * 0.125f - m0n);
            float p02 = __expf(sc[2 * j][2] * 0.125f - m1n);
            float p03 = __expf(sc[2 * j][3] * 0.125f - m1n);
            float p10 = __expf(sc[2 * j + 1][0] * 0.125f - m0n);
            float p11 = __expf(sc[2 * j + 1][1] * 0.125f - m0n);
            float p12 = __expf(sc[2 * j + 1][2] * 0.125f - m1n);
            float p13 = __expf(sc[2 * j + 1][3] * 0.125f - m1n);
            s0 += p00 + p01 + p10 + p11;
            s1 += p02 + p03 + p12 + p13;
            __half2 h;
            h = __floats2half2_rn(p00, p01); ap[j][0] = *(uint32_t*)&h;
            h = __floats2half2_rn(p02, p03); ap[j][1] = *(uint32_t*)&h;
            h = __floats2half2_rn(p10, p11); ap[j][2] = *(uint32_t*)&h;
            h = __floats2half2_rn(p12, p13); ap[j][3] = *(uint32_t*)&h;
        }
        l0 += s0; l1 += s1;

        const uint32_t vb = kb + AST_K;
#pragma unroll
        for (int j = 0; j < 4; j++) {
            const uint32_t nl = (uint32_t)(j * 16) + vnodeb;
#pragma unroll
            for (int dd = 0; dd < 4; dd++) {
                const uint32_t vchunk = (uint32_t)(2 * dd + (lm >> 1));
                uint32_t b0, b1, b2, b3;
                ldsm4t(b0, b1, b2, b3, vb + nl * 128 + ((vchunk ^ lrr) << 4));
                uint32_t bfa[2] = {b0, b1}, bfb[2] = {b2, b3};
                mma_f16(Oa[2 * dd], ap[j], bfa);
                mma_f16(Oa[2 * dd + 1], ap[j], bfb);
            }
        }
    }

    l0 += __shfl_xor_sync(0xffffffffu, l0, 1);
    l0 += __shfl_xor_sync(0xffffffffu, l0, 2);
    l1 += __shfl_xor_sync(0xffffffffu, l1, 1);
    l1 += __shfl_xor_sync(0xffffffffu, l1, 2);
    const float inv0 = 1.f / l0, inv1 = 1.f / l1;
    const size_t rowg = (nb + qrow0 + w * 16 + g) * 1024 + hh * 64;
#pragma unroll
    for (int ntd = 0; ntd < 8; ntd++) {
        int col = ntd * 8 + 2 * t;
        __half2 h0 = __floats2half2_rn(Oa[ntd][0] * inv0, Oa[ntd][1] * inv0);
        __half2 h1 = __floats2half2_rn(Oa[ntd][2] * inv1, Oa[ntd][3] * inv1);
        *(__half2*)(oh + rowg + col) = h0;
        *(__half2*)(oh + rowg + 8 * 1024 + col) = h1;
    }
}

// ---------------- LayerNorm: fp16 input, stats in fp32 ----------------
template <bool OUTF>
__global__ void __launch_bounds__(256) ln_h(
    const __half* __restrict__ X,
    const float* __restrict__ gamma, const float* __restrict__ beta,
    float* __restrict__ outf, __half* __restrict__ outh)
{
    const int row = blockIdx.x;
    const int tid = threadIdx.x;
    uint2 u = ((const uint2*)(X + (size_t)row * DIM))[tid];
    float2 p0 = __half22float2(*(__half2*)&u.x);
    float2 p1 = __half22float2(*(__half2*)&u.y);
    float4 s = {p0.x, p0.y, p1.x, p1.y};
    float sum = s.x + s.y + s.z + s.w;
    float sq  = s.x * s.x + s.y * s.y + s.z * s.z + s.w * s.w;

    __shared__ float red[16];
#pragma unroll
    for (int off = 16; off; off >>= 1) {
        sum += __shfl_xor_sync(0xffffffffu, sum, off);
        sq  += __shfl_xor_sync(0xffffffffu, sq, off);
    }
    const int warp = tid >> 5, lane = tid & 31;
    if (lane == 0) { red[warp] = sum; red[8 + warp] = sq; }
    __syncthreads();
    sum = 0.f; sq = 0.f;
#pragma unroll
    for (int w = 0; w < 8; w++) { sum += red[w]; sq += red[8 + w]; }

    const float mean = sum * (1.0f / DIM);
    const float var  = sq * (1.0f / DIM) - mean * mean;
    const float inv  = rsqrtf(var + 1e-5f);
    const float4 gm = ((const float4*)gamma)[tid];
    const float4 be = ((const float4*)beta)[tid];
    float4 o;
    o.x = (s.x - mean) * inv * gm.x + be.x;
    o.y = (s.y - mean) * inv * gm.y + be.y;
    o.z = (s.z - mean) * inv * gm.z + be.z;
    o.w = (s.w - mean) * inv * gm.w + be.w;
    if (OUTF) {
        ((float4*)(outf + (size_t)row * DIM))[tid] = o;
    } else {
        __half2 h0 = __floats2half2_rn(o.x, o.y);
        __half2 h1 = __floats2half2_rn(o.z, o.w);
        uint2 w2; w2.x = *(uint32_t*)&h0; w2.y = *(uint32_t*)&h1;
        ((uint2*)(outh + (size_t)row * DIM))[tid] = w2;
    }
}

// ---------------- launcher ----------------
extern "C" void kernel_launch(void* const* d_in, const int* in_sizes, int n_in,
                              void* d_out, int out_size)
{
    const float* h     = (const float*)d_in[0];
    const float* w_in  = (const float*)d_in[1];
    const float* b_in  = (const float*)d_in[2];
    const float* w_out = (const float*)d_in[3];
    const float* b_out = (const float*)d_in[4];
    const float* ln1g  = (const float*)d_in[5];
    const float* ln1b  = (const float*)d_in[6];
    const float* ln2g  = (const float*)d_in[7];
    const float* ln2b  = (const float*)d_in[8];
    const float* fw1   = (const float*)d_in[9];
    const float* fb1   = (const float*)d_in[10];
    const float* fw2   = (const float*)d_in[11];
    const float* fb2   = (const float*)d_in[12];
    float* out = (float*)d_out;

    __half *h_h, *qkv_h, *attn_h, *x1_h, *tmp_h, *f1_h, *win_h, *wout_h, *fw1_h, *fw2_h;
    cudaGetSymbolAddress((void**)&h_h,    g_h_h);
    cudaGetSymbolAddress((void**)&qkv_h,  g_qkv_h);
    cudaGetSymbolAddress((void**)&attn_h, g_attn_h);
    cudaGetSymbolAddress((void**)&x1_h,   g_x1_h);
    cudaGetSymbolAddress((void**)&tmp_h,  g_tmp_h);
    cudaGetSymbolAddress((void**)&f1_h,   g_f1_h);
    cudaGetSymbolAddress((void**)&win_h,  g_win_h);
    cudaGetSymbolAddress((void**)&wout_h, g_wout_h);
    cudaGetSymbolAddress((void**)&fw1_h,  g_fw1_h);
    cudaGetSymbolAddress((void**)&fw2_h,  g_fw2_h);

    cudaFuncSetAttribute(gemm_h<false, false>,
                         cudaFuncAttributeMaxDynamicSharedMemorySize, GEMM_SMEM);
    cudaFuncSetAttribute(gemm_h<false, true>,
                         cudaFuncAttributeMaxDynamicSharedMemorySize, GEMM_SMEM);
    cudaFuncSetAttribute(gemm_h<true, false>,
                         cudaFuncAttributeMaxDynamicSharedMemorySize, GEMM_SMEM);
    cudaFuncSetAttribute(attn_flash,
                         cudaFuncAttributeMaxDynamicSharedMemorySize, ATTN_SMEM);

    // 0) fp16 conversions (single launch)
    f32_to_f16_all<<<(CNT + 255) / 256, 256>>>(
        h, h_h, w_in, win_h, w_out, wout_h, fw1, fw1_h, fw2, fw2_h);

    // 1) QKV
    gemm_h<false, false><<<dim3(3 * DIM / BN, T_NODES / BM), 256, GEMM_SMEM>>>(
        h_h, win_h, b_in, qkv_h, nullptr, T_NODES, 3 * DIM, DIM);
    // 2) attention (flash)
    attn_flash<<<dim3(4, NHEAD, NGRAPH), 256, ATTN_SMEM>>>(qkv_h, attn_h);
    // 3) out-proj + residual(h_h) -> tmp_h
    gemm_h<false, true><<<dim3(DIM / BN, T_NODES / BM), 256, GEMM_SMEM>>>(
        attn_h, wout_h, b_out, tmp_h, h_h, T_NODES, DIM, DIM);
    // 4) x1_h = LN1(tmp_h)
    ln_h<false><<<T_NODES, 256>>>(tmp_h, ln1g, ln1b, nullptr, x1_h);
    // 5) FFN1 + ReLU
    gemm_h<true, false><<<dim3(2 * DIM / BN, T_NODES / BM), 256, GEMM_SMEM>>>(
        x1_h, fw1_h, fb1, f1_h, nullptr, T_NODES, 2 * DIM, DIM);
    // 6) FFN2 + residual(x1_h) -> tmp_h
    gemm_h<false, true><<<dim3(DIM / BN, T_NODES / BM), 256, GEMM_SMEM>>>(
        f1_h, fw2_h, fb2, tmp_h, x1_h, T_NODES, DIM, 2 * DIM);
    // 7) out = LN2(tmp_h)
    ln_h<true><<<T_NODES, 256>>>(tmp_h, ln2g, ln2b, out, nullptr);
}